// round 14
// baseline (speedup 1.0000x reference)
#include <cuda_runtime.h>
#include <cstdint>

#define BATCHES 64
#define NPTS    (1<<18)
#define NCL     8
#define NITER   10
#define CAND_CAP 1024
#define K2_THRESH (1u<<22)
#define NBUCK 2048
#define LCAP 224
#define BPB 9                 // blocks per batch in persistent Lloyd (576 <= 592 resident)

__device__ unsigned g_key1[(size_t)BATCHES * NPTS];
__device__ float g_soax[(size_t)BATCHES * NPTS];   // SoA pixel cache (written iter 0)
__device__ float g_soay[(size_t)BATCHES * NPTS];
__device__ float g_soaz[(size_t)BATCHES * NPTS];
__device__ unsigned long long g_cand[BATCHES * CAND_CAP];
__device__ int g_cand_cnt[BATCHES];
__device__ uint2 g_sub1[BATCHES], g_sub2[BATCHES];
__device__ int g_hist[BATCHES * NBUCK];
__device__ int g_tbuck[BATCHES * NCL];
__device__ int g_trank[BATCHES * NCL];
__device__ unsigned long long g_list[BATCHES * NCL * LCAP];
__device__ int g_lcnt[BATCHES * NCL];
__device__ float g_cent[BATCHES * NCL * 3];
__device__ float g_sums[BATCHES * NCL * 4];
__device__ int g_done[BATCHES];
__device__ int g_gen[BATCHES];

// ---------------- Threefry-2x32 (JAX-compatible) ----------------
__device__ __forceinline__ void tf2x32(unsigned k0, unsigned k1,
                                       unsigned x0, unsigned x1,
                                       unsigned &o0, unsigned &o1) {
  unsigned k2 = k0 ^ k1 ^ 0x1BD11BDAu;
  x0 += k0; x1 += k1;
#define TF_R(r) { x0 += x1; x1 = __funnelshift_l(x1, x1, (r)); x1 ^= x0; }
  TF_R(13) TF_R(15) TF_R(26) TF_R(6)  x0 += k1; x1 += k2 + 1u;
  TF_R(17) TF_R(29) TF_R(16) TF_R(24) x0 += k2; x1 += k0 + 2u;
  TF_R(13) TF_R(15) TF_R(26) TF_R(6)  x0 += k0; x1 += k1 + 3u;
  TF_R(17) TF_R(29) TF_R(16) TF_R(24) x0 += k1; x1 += k2 + 4u;
  TF_R(13) TF_R(15) TF_R(26) TF_R(6)  x0 += k2; x1 += k0 + 5u;
#undef TF_R
  o0 = x0; o1 = x1;
}

__global__ void k_init() {
  int gid = blockIdx.x * blockDim.x + threadIdx.x;
  if (gid < 64) {
    int b = gid;
    unsigned a0, a1, n0, n1, s0, s1;
    tf2x32(0u, 42u, 0u, (unsigned)b, a0, a1);
    tf2x32(a0, a1, 0u, 0u, n0, n1);
    tf2x32(a0, a1, 0u, 1u, s0, s1);
    g_sub1[b] = make_uint2(s0, s1);
    tf2x32(n0, n1, 0u, 1u, s0, s1);
    g_sub2[b] = make_uint2(s0, s1);
    g_cand_cnt[b] = 0;
    g_done[b] = 0;
    g_gen[b] = 0;
  }
  if (gid < BATCHES * NCL) g_lcnt[gid] = 0;
  if (gid < BATCHES * NBUCK) g_hist[gid] = 0;
}

// key2 candidate filter + key1 store + key1 histogram. 4096 blocks. (proven)
__global__ void __launch_bounds__(256) k_genA() {
  int blk = blockIdx.x;
  int b = blk >> 6;
  unsigned base = (unsigned)(blk & 63) * 4096u;
  uint2 s1 = g_sub1[b], s2 = g_sub2[b];
  int* hist = g_hist + b * NBUCK;
  unsigned* keyp = g_key1 + (size_t)b * NPTS;
  #pragma unroll 4
  for (int k = 0; k < 16; ++k) {
    unsigned i = base + threadIdx.x + (unsigned)k * 256u;
    unsigned y0, y1;
    tf2x32(s2.x, s2.y, 0u, i, y0, y1);
    unsigned k2v = y0 ^ y1;
    if (k2v < K2_THRESH) {
      int slot = atomicAdd(&g_cand_cnt[b], 1);
      if (slot < CAND_CAP)
        g_cand[b * CAND_CAP + slot] = ((unsigned long long)k2v << 32) | i;
    }
    tf2x32(s1.x, s1.y, 0u, i, y0, y1);
    unsigned key = y0 ^ y1;
    keyp[i] = key;
    atomicAdd(&hist[key >> 21], 1);
  }
}

// per batch: top-8 (key2,pos) -> global ranks -> (bucket, in-bucket rank)
__global__ void __launch_bounds__(1024) k_pick() {
  int b = blockIdx.x;
  int t = threadIdx.x;
  __shared__ unsigned long long s_cand[CAND_CAP];
  __shared__ int s_rank[8];
  __shared__ int h[NBUCK];
  __shared__ int c[64];
  __shared__ unsigned long long s_min;

  int cnt = g_cand_cnt[b]; if (cnt > CAND_CAP) cnt = CAND_CAP;
  s_cand[t] = (t < cnt) ? g_cand[b * CAND_CAP + t] : ~0ull;
  h[t] = g_hist[b * NBUCK + t];
  h[t + 1024] = g_hist[b * NBUCK + t + 1024];
  __syncthreads();
  for (int k = 0; k < 8; ++k) {
    if (t == 0) s_min = ~0ull;
    __syncthreads();
    atomicMin(&s_min, s_cand[t]);
    __syncthreads();
    unsigned long long m = s_min;
    if (t == 0) s_rank[k] = (int)(m & 0xffffffffull);
    if (s_cand[t] == m) s_cand[t] = ~0ull;
    __syncthreads();
  }
  if (t < 64) {
    int s = 0;
    #pragma unroll
    for (int q = 0; q < 32; ++q) s += h[t * 32 + q];
    c[t] = s;
  }
  __syncthreads();
  if (t == 0) {
    int run = 0;
    for (int w = 0; w < 64; ++w) { int v = c[w]; c[w] = run; run += v; }
  }
  __syncthreads();
  if (t < 8) {
    int r = s_rank[t];
    int w = 0;
    for (int q = 0; q < 64; ++q) if (c[q] <= r) w = q;
    int rem = r - c[w];
    int d = w * 32;
    for (int q = 0; q < 32; ++q) {
      int hv = h[w * 32 + q];
      if (rem < hv) { d = w * 32 + q; break; }
      rem -= hv;
    }
    g_tbuck[b * 8 + t] = d;
    g_trank[b * 8 + t] = rem;
  }
}

// scan stored key1, bucket bitmap fast-path, collect target buckets.
__global__ void __launch_bounds__(256) k_collect() {
  int blk = blockIdx.x;
  int b = blk >> 6;
  unsigned base = (unsigned)(blk & 63) * 4096u;
  const unsigned* __restrict__ keyp = g_key1 + (size_t)b * NPTS;
  __shared__ unsigned bm[NBUCK / 32];     // 2048-bit bucket membership bitmap
  int tb[8];
  #pragma unroll
  for (int j = 0; j < 8; ++j) tb[j] = g_tbuck[b * 8 + j];
  if (threadIdx.x < 64) bm[threadIdx.x] = 0u;
  __syncthreads();
  if (threadIdx.x < 8) {
    int d = tb[threadIdx.x];
    atomicOr(&bm[d >> 5], 1u << (d & 31));
  }
  __syncthreads();
  #pragma unroll 4
  for (int k = 0; k < 16; ++k) {
    unsigned i = base + threadIdx.x + (unsigned)k * 256u;
    unsigned key = keyp[i];
    unsigned bu = key >> 21;
    if ((bm[bu >> 5] >> (bu & 31)) & 1u) {       // rare (~8/2048 buckets)
      #pragma unroll
      for (int j = 0; j < 8; ++j)
        if ((int)bu == tb[j]) {
          int s = atomicAdd(&g_lcnt[b * 8 + j], 1);
          if (s < LCAP)
            g_list[(b * 8 + j) * LCAP + s] =
                ((unsigned long long)(key & 0x1FFFFFu) << 32) | i;
        }
    }
  }
}

// per (batch,target): pick rank-r entry by (key1_low, idx); write centroid.
__global__ void __launch_bounds__(256) k_final(const float* __restrict__ in) {
  int b = blockIdx.x;
  int t = threadIdx.x;
  int j = t >> 5, lane = t & 31;
  __shared__ unsigned long long sl[8][LCAP];
  int n = g_lcnt[b * 8 + j]; if (n > LCAP) n = LCAP;
  for (int q = lane; q < n; q += 32)
    sl[j][q] = g_list[(b * 8 + j) * LCAP + q];
  __syncwarp();
  int r = g_trank[b * 8 + j];
  for (int q = lane; q < n; q += 32) {
    unsigned long long e = sl[j][q];
    int rk = 0;
    for (int p = 0; p < n; ++p) rk += (sl[j][p] < e);
    if (rk == r) {
      unsigned idx = (unsigned)(e & 0xffffffffull);
      const float* px = in + ((size_t)b * NPTS + idx) * 3;
      float* cc = g_cent + (b * 8 + j) * 3;
      cc[0] = px[0]; cc[1] = px[1]; cc[2] = px[2];
    }
  }
  if (t < 32) g_sums[b * 32 + t] = 0.f;
}

// ---- persistent Lloyd: iter0 AoS (+SoA store), iters 1-9 coalesced SoA ----
__global__ void __launch_bounds__(256, 4) k_lloyd(const float* __restrict__ in,
                                                  float* __restrict__ out) {
  int b   = blockIdx.x / BPB;
  int blk = blockIdx.x - b * BPB;
  int tid = threadIdx.x;
  __shared__ float s_acc[8][4][256];    // 32 KB

  int ch0 = blk * 28 + min(blk, 4);
  int nch = 28 + (blk < 4 ? 1 : 0);     // 1024-pt groups owned by this block
  size_t pbase = (size_t)b * NPTS + (size_t)ch0 * 1024;
  const float4* gp = (const float4*)in + pbase * 3 / 4;
  float4* sx4 = (float4*)(g_soax + pbase);
  float4* sy4 = (float4*)(g_soay + pbase);
  float4* sz4 = (float4*)(g_soaz + pbase);

  for (int it = 0; it < NITER; ++it) {
    float n0[8], n1[8], n2[8], bb[8];
    const float* cent = g_cent + b * 24;
    #pragma unroll
    for (int c = 0; c < 8; ++c) {
      float a = cent[c*3+0], d = cent[c*3+1], e = cent[c*3+2];
      n0[c] = -2.f*a; n1[c] = -2.f*d; n2[c] = -2.f*e;
      bb[c] = a*a + d*d + e*e + 6.f;   // positive scores: uint cmp == float cmp
    }
    for (int i = tid; i < 8*4*256; i += 256) (&s_acc[0][0][0])[i] = 0.f;
    __syncthreads();   // accumulators zeroed before any thread writes

    unsigned long long cnt8 = 0ull;    // 8x 8-bit per-cluster counters (max 116)

    // per-point classify+accumulate (identical FMA order on both paths)
    auto body = [&](float x0, float x1, float x2) {
      unsigned u[8];
      #pragma unroll
      for (int c = 0; c < 8; ++c) {
        float s = fmaf(x2, n2[c], fmaf(x1, n1[c], fmaf(x0, n0[c], bb[c])));
        u[c] = (__float_as_uint(s) & 0xFFFFFFF8u) | (unsigned)c;
      }
      unsigned m = min(min(min(u[0],u[1]),min(u[2],u[3])),
                       min(min(u[4],u[5]),min(u[6],u[7])));
      unsigned bi = m & 7u;
      float* a = &s_acc[0][0][0] + bi * 1024 + tid;
      a[0]   += x0;
      a[256] += x1;
      a[512] += x2;
      cnt8 += 1ull << (bi << 3);
    };

    if (it == 0) {
      // AoS path: strided float4 triplet; also emit coalesced SoA cache
      const float4* tp = gp + tid * 3;
      for (int g = 0; g < nch; ++g) {
        float4 A = tp[0], B4 = tp[1], C = tp[2];
        tp += 768;
        float qx[4] = {A.x, A.w, B4.z, C.y};
        float qy[4] = {A.y, B4.x, B4.w, C.z};
        float qz[4] = {A.z, B4.y, C.x,  C.w};
        sx4[g * 256 + tid] = make_float4(qx[0], qx[1], qx[2], qx[3]);
        sy4[g * 256 + tid] = make_float4(qy[0], qy[1], qy[2], qy[3]);
        sz4[g * 256 + tid] = make_float4(qz[0], qz[1], qz[2], qz[3]);
        #pragma unroll
        for (int q = 0; q < 4; ++q) body(qx[q], qy[q], qz[q]);
      }
    } else {
      // SoA path: 3 perfectly coalesced LDG.128 per 4 points
      #pragma unroll 2
      for (int g = 0; g < nch; ++g) {
        float4 X = sx4[g * 256 + tid];
        float4 Y = sy4[g * 256 + tid];
        float4 Z = sz4[g * 256 + tid];
        body(X.x, Y.x, Z.x);
        body(X.y, Y.y, Z.y);
        body(X.z, Y.z, Z.z);
        body(X.w, Y.w, Z.w);
      }
    }

    // expand packed counts into the count plane (once per iteration)
    #pragma unroll
    for (int c = 0; c < 8; ++c)
      s_acc[c][3][tid] = (float)((unsigned)(cnt8 >> (c << 3)) & 255u);
    __syncthreads();

    int w = tid >> 5, lane = tid & 31;   // warp w reduces cluster w
    float r0=0.f, r1=0.f, r2=0.f, r3=0.f;
    #pragma unroll
    for (int k = 0; k < 8; ++k) {
      r0 += s_acc[w][0][lane + 32*k];
      r1 += s_acc[w][1][lane + 32*k];
      r2 += s_acc[w][2][lane + 32*k];
      r3 += s_acc[w][3][lane + 32*k];
    }
    #pragma unroll
    for (int o = 16; o; o >>= 1) {
      r0 += __shfl_down_sync(0xffffffffu, r0, o);
      r1 += __shfl_down_sync(0xffffffffu, r1, o);
      r2 += __shfl_down_sync(0xffffffffu, r2, o);
      r3 += __shfl_down_sync(0xffffffffu, r3, o);
    }
    if (lane == 0) {
      float* gs = g_sums + b * 32 + w * 4;
      atomicAdd(gs+0, r0); atomicAdd(gs+1, r1);
      atomicAdd(gs+2, r2); atomicAdd(gs+3, r3);
      __threadfence();
    }
    __syncthreads();

    if (tid == 0) {
      int old = atomicAdd(&g_done[b], 1);
      if (old == BPB - 1) {
        __threadfence();
        float* gs = g_sums + b * 32;
        float* cc = g_cent + b * 24;
        #pragma unroll
        for (int c = 0; c < 8; ++c) {
          float sx = gs[c*4+0], sy = gs[c*4+1], sz = gs[c*4+2], cn = gs[c*4+3];
          float ox, oy, oz;
          if (cn > 0.f) { ox = sx/cn; oy = sy/cn; oz = sz/cn; }
          else          { ox = cc[c*3]; oy = cc[c*3+1]; oz = cc[c*3+2]; }
          cc[c*3] = ox; cc[c*3+1] = oy; cc[c*3+2] = oz;
          gs[c*4] = 0.f; gs[c*4+1] = 0.f; gs[c*4+2] = 0.f; gs[c*4+3] = 0.f;
          if (it == NITER - 1) {
            out[b*24 + c*3 + 0] = ox;
            out[b*24 + c*3 + 1] = oy;
            out[b*24 + c*3 + 2] = oz;
          }
        }
        g_done[b] = 0;
        __threadfence();
        atomicAdd(&g_gen[b], 1);
      }
      int target = it + 1;
      unsigned g;
      do {
        asm volatile("ld.acquire.gpu.u32 %0, [%1];"
                     : "=r"(g) : "l"(&g_gen[b]) : "memory");
        if ((int)g < target) __nanosleep(64);
      } while ((int)g < target);
    }
    __syncthreads();
  }
}

extern "C" void kernel_launch(void* const* d_in, const int* in_sizes, int n_in,
                              void* d_out, int out_size) {
  const float* in = (const float*)d_in[0];
  float* out = (float*)d_out;
  k_init<<<256, 512>>>();
  k_genA<<<4096, 256>>>();
  k_pick<<<BATCHES, 1024>>>();
  k_collect<<<4096, 256>>>();
  k_final<<<BATCHES, 256>>>(in);
  k_lloyd<<<BATCHES * BPB, 256>>>(in, out);
}

// round 15
// speedup vs baseline: 1.1054x; 1.1054x over previous
#include <cuda_runtime.h>
#include <cstdint>

#define BATCHES 64
#define NPTS    (1<<18)
#define NCL     8
#define NITER   10
#define CAND_CAP 1024
#define K2_THRESH (1u<<22)
#define NBUCK 2048
#define LCAP 224
#define BPB 9                 // blocks per batch in persistent Lloyd (576 <= 592 resident)

__device__ unsigned g_key1[(size_t)BATCHES * NPTS];
__device__ unsigned long long g_cand[BATCHES * CAND_CAP];
__device__ int g_cand_cnt[BATCHES];
__device__ uint2 g_sub1[BATCHES], g_sub2[BATCHES];
__device__ int g_hist[BATCHES * NBUCK];
__device__ int g_tbuck[BATCHES * NCL];
__device__ int g_trank[BATCHES * NCL];
__device__ unsigned long long g_list[BATCHES * NCL * LCAP];
__device__ int g_lcnt[BATCHES * NCL];
__device__ float g_cent[BATCHES * NCL * 3];
__device__ float g_sums[BATCHES * NCL * 4];
__device__ int g_done[BATCHES];
__device__ int g_gen[BATCHES];

// ---------------- Threefry-2x32 (JAX-compatible) ----------------
__device__ __forceinline__ void tf2x32(unsigned k0, unsigned k1,
                                       unsigned x0, unsigned x1,
                                       unsigned &o0, unsigned &o1) {
  unsigned k2 = k0 ^ k1 ^ 0x1BD11BDAu;
  x0 += k0; x1 += k1;
#define TF_R(r) { x0 += x1; x1 = __funnelshift_l(x1, x1, (r)); x1 ^= x0; }
  TF_R(13) TF_R(15) TF_R(26) TF_R(6)  x0 += k1; x1 += k2 + 1u;
  TF_R(17) TF_R(29) TF_R(16) TF_R(24) x0 += k2; x1 += k0 + 2u;
  TF_R(13) TF_R(15) TF_R(26) TF_R(6)  x0 += k0; x1 += k1 + 3u;
  TF_R(17) TF_R(29) TF_R(16) TF_R(24) x0 += k1; x1 += k2 + 4u;
  TF_R(13) TF_R(15) TF_R(26) TF_R(6)  x0 += k2; x1 += k0 + 5u;
#undef TF_R
  o0 = x0; o1 = x1;
}

__global__ void k_init() {
  int gid = blockIdx.x * blockDim.x + threadIdx.x;
  if (gid < 64) {
    int b = gid;
    unsigned a0, a1, n0, n1, s0, s1;
    tf2x32(0u, 42u, 0u, (unsigned)b, a0, a1);
    tf2x32(a0, a1, 0u, 0u, n0, n1);
    tf2x32(a0, a1, 0u, 1u, s0, s1);
    g_sub1[b] = make_uint2(s0, s1);
    tf2x32(n0, n1, 0u, 1u, s0, s1);
    g_sub2[b] = make_uint2(s0, s1);
    g_cand_cnt[b] = 0;
    g_done[b] = 0;
    g_gen[b] = 0;
  }
  if (gid < BATCHES * NCL) g_lcnt[gid] = 0;
  if (gid < BATCHES * NBUCK) g_hist[gid] = 0;
}

// key2 candidate filter + key1 store + key1 histogram. 4096 blocks. (proven)
__global__ void __launch_bounds__(256) k_genA() {
  int blk = blockIdx.x;
  int b = blk >> 6;
  unsigned base = (unsigned)(blk & 63) * 4096u;
  uint2 s1 = g_sub1[b], s2 = g_sub2[b];
  int* hist = g_hist + b * NBUCK;
  unsigned* keyp = g_key1 + (size_t)b * NPTS;
  #pragma unroll 4
  for (int k = 0; k < 16; ++k) {
    unsigned i = base + threadIdx.x + (unsigned)k * 256u;
    unsigned y0, y1;
    tf2x32(s2.x, s2.y, 0u, i, y0, y1);
    unsigned k2v = y0 ^ y1;
    if (k2v < K2_THRESH) {
      int slot = atomicAdd(&g_cand_cnt[b], 1);
      if (slot < CAND_CAP)
        g_cand[b * CAND_CAP + slot] = ((unsigned long long)k2v << 32) | i;
    }
    tf2x32(s1.x, s1.y, 0u, i, y0, y1);
    unsigned key = y0 ^ y1;
    keyp[i] = key;
    atomicAdd(&hist[key >> 21], 1);
  }
}

// per batch: top-8 (key2,pos) -> global ranks -> (bucket, in-bucket rank)
__global__ void __launch_bounds__(1024) k_pick() {
  int b = blockIdx.x;
  int t = threadIdx.x;
  __shared__ unsigned long long s_cand[CAND_CAP];
  __shared__ int s_rank[8];
  __shared__ int h[NBUCK];
  __shared__ int c[64];
  __shared__ unsigned long long s_min;

  int cnt = g_cand_cnt[b]; if (cnt > CAND_CAP) cnt = CAND_CAP;
  s_cand[t] = (t < cnt) ? g_cand[b * CAND_CAP + t] : ~0ull;
  h[t] = g_hist[b * NBUCK + t];
  h[t + 1024] = g_hist[b * NBUCK + t + 1024];
  __syncthreads();
  for (int k = 0; k < 8; ++k) {
    if (t == 0) s_min = ~0ull;
    __syncthreads();
    atomicMin(&s_min, s_cand[t]);
    __syncthreads();
    unsigned long long m = s_min;
    if (t == 0) s_rank[k] = (int)(m & 0xffffffffull);
    if (s_cand[t] == m) s_cand[t] = ~0ull;
    __syncthreads();
  }
  if (t < 64) {
    int s = 0;
    #pragma unroll
    for (int q = 0; q < 32; ++q) s += h[t * 32 + q];
    c[t] = s;
  }
  __syncthreads();
  if (t == 0) {
    int run = 0;
    for (int w = 0; w < 64; ++w) { int v = c[w]; c[w] = run; run += v; }
  }
  __syncthreads();
  if (t < 8) {
    int r = s_rank[t];
    int w = 0;
    for (int q = 0; q < 64; ++q) if (c[q] <= r) w = q;
    int rem = r - c[w];
    int d = w * 32;
    for (int q = 0; q < 32; ++q) {
      int hv = h[w * 32 + q];
      if (rem < hv) { d = w * 32 + q; break; }
      rem -= hv;
    }
    g_tbuck[b * 8 + t] = d;
    g_trank[b * 8 + t] = rem;
  }
}

// scan stored key1, bucket bitmap fast-path, collect target buckets. (42us proven)
__global__ void __launch_bounds__(256) k_collect() {
  int blk = blockIdx.x;
  int b = blk >> 6;
  unsigned base = (unsigned)(blk & 63) * 4096u;
  const unsigned* __restrict__ keyp = g_key1 + (size_t)b * NPTS;
  __shared__ unsigned bm[NBUCK / 32];     // 2048-bit bucket membership bitmap
  int tb[8];
  #pragma unroll
  for (int j = 0; j < 8; ++j) tb[j] = g_tbuck[b * 8 + j];
  if (threadIdx.x < 64) bm[threadIdx.x] = 0u;
  __syncthreads();
  if (threadIdx.x < 8) {
    int d = tb[threadIdx.x];
    atomicOr(&bm[d >> 5], 1u << (d & 31));
  }
  __syncthreads();
  #pragma unroll 4
  for (int k = 0; k < 16; ++k) {
    unsigned i = base + threadIdx.x + (unsigned)k * 256u;
    unsigned key = keyp[i];
    unsigned bu = key >> 21;
    if ((bm[bu >> 5] >> (bu & 31)) & 1u) {       // rare (~8/2048 buckets)
      #pragma unroll
      for (int j = 0; j < 8; ++j)
        if ((int)bu == tb[j]) {
          int s = atomicAdd(&g_lcnt[b * 8 + j], 1);
          if (s < LCAP)
            g_list[(b * 8 + j) * LCAP + s] =
                ((unsigned long long)(key & 0x1FFFFFu) << 32) | i;
        }
    }
  }
}

// per (batch,target): pick rank-r entry by (key1_low, idx); write centroid.
__global__ void __launch_bounds__(256) k_final(const float* __restrict__ in) {
  int b = blockIdx.x;
  int t = threadIdx.x;
  int j = t >> 5, lane = t & 31;
  __shared__ unsigned long long sl[8][LCAP];
  int n = g_lcnt[b * 8 + j]; if (n > LCAP) n = LCAP;
  for (int q = lane; q < n; q += 32)
    sl[j][q] = g_list[(b * 8 + j) * LCAP + q];
  __syncwarp();
  int r = g_trank[b * 8 + j];
  for (int q = lane; q < n; q += 32) {
    unsigned long long e = sl[j][q];
    int rk = 0;
    for (int p = 0; p < n; ++p) rk += (sl[j][p] < e);
    if (rk == r) {
      unsigned idx = (unsigned)(e & 0xffffffffull);
      const float* px = in + ((size_t)b * NPTS + idx) * 3;
      float* cc = g_cent + (b * 8 + j) * 3;
      cc[0] = px[0]; cc[1] = px[1]; cc[2] = px[2];
    }
  }
  if (t < 32) g_sums[b * 32 + t] = 0.f;
}

// ---- persistent Lloyd: direct float4 LDG, barrier-free inner loop (R13-proven) ----
__global__ void __launch_bounds__(256, 4) k_lloyd(const float* __restrict__ in,
                                                  float* __restrict__ out) {
  int b   = blockIdx.x / BPB;
  int blk = blockIdx.x - b * BPB;
  int tid = threadIdx.x;
  __shared__ float s_acc[8][4][256];    // 32 KB

  int ch0 = blk * 28 + min(blk, 4);
  int nch = 28 + (blk < 4 ? 1 : 0);     // 1024-pt groups owned by this block
  const float4* gp = (const float4*)in + (size_t)b * (NPTS*3/4)
                                       + (size_t)ch0 * 768;

  for (int it = 0; it < NITER; ++it) {
    float n0[8], n1[8], n2[8], bb[8];
    const float* cent = g_cent + b * 24;
    #pragma unroll
    for (int c = 0; c < 8; ++c) {
      float a = cent[c*3+0], d = cent[c*3+1], e = cent[c*3+2];
      n0[c] = -2.f*a; n1[c] = -2.f*d; n2[c] = -2.f*e;
      bb[c] = a*a + d*d + e*e + 6.f;   // positive scores: uint cmp == float cmp
    }
    {
      float4* z4 = (float4*)&s_acc[0][0][0];
      #pragma unroll
      for (int i = 0; i < 8; ++i)
        z4[i * 256 + tid] = make_float4(0.f, 0.f, 0.f, 0.f);
    }
    __syncthreads();   // accumulators zeroed before any thread writes

    unsigned long long cnt8 = 0ull;    // 8x 8-bit per-cluster counters (max 116)

    // barrier-free: each thread owns its accumulator column; 4 pts per group
    const float4* tp = gp + tid * 3;
    #pragma unroll 2
    for (int g = 0; g < nch; ++g) {
      float4 A = tp[0], B4 = tp[1], C = tp[2];
      tp += 768;
      float qx[4] = {A.x, A.w, B4.z, C.y};
      float qy[4] = {A.y, B4.x, B4.w, C.z};
      float qz[4] = {A.z, B4.y, C.x,  C.w};
      #pragma unroll
      for (int q = 0; q < 4; ++q) {
        float x0 = qx[q], x1 = qy[q], x2 = qz[q];
        unsigned u[8];
        #pragma unroll
        for (int c = 0; c < 8; ++c) {
          float s = fmaf(x2, n2[c], fmaf(x1, n1[c], fmaf(x0, n0[c], bb[c])));
          u[c] = (__float_as_uint(s) & 0xFFFFFFF8u) | (unsigned)c;
        }
        unsigned m = min(min(min(u[0],u[1]),min(u[2],u[3])),
                         min(min(u[4],u[5]),min(u[6],u[7])));
        unsigned bi = m & 7u;
        float* a = &s_acc[0][0][0] + bi * 1024 + tid;
        a[0]   += x0;
        a[256] += x1;
        a[512] += x2;
        cnt8 += 1ull << (bi << 3);
      }
    }
    // expand packed counts into the count plane (once per iteration)
    #pragma unroll
    for (int c = 0; c < 8; ++c)
      s_acc[c][3][tid] = (float)((unsigned)(cnt8 >> (c << 3)) & 255u);
    __syncthreads();

    int w = tid >> 5, lane = tid & 31;   // warp w reduces cluster w
    float r0=0.f, r1=0.f, r2=0.f, r3=0.f;
    #pragma unroll
    for (int k = 0; k < 8; ++k) {
      r0 += s_acc[w][0][lane + 32*k];
      r1 += s_acc[w][1][lane + 32*k];
      r2 += s_acc[w][2][lane + 32*k];
      r3 += s_acc[w][3][lane + 32*k];
    }
    #pragma unroll
    for (int o = 16; o; o >>= 1) {
      r0 += __shfl_down_sync(0xffffffffu, r0, o);
      r1 += __shfl_down_sync(0xffffffffu, r1, o);
      r2 += __shfl_down_sync(0xffffffffu, r2, o);
      r3 += __shfl_down_sync(0xffffffffu, r3, o);
    }
    if (lane == 0) {
      float* gs = g_sums + b * 32 + w * 4;
      atomicAdd(gs+0, r0); atomicAdd(gs+1, r1);
      atomicAdd(gs+2, r2); atomicAdd(gs+3, r3);
      __threadfence();
    }
    __syncthreads();

    if (tid == 0) {
      int old = atomicAdd(&g_done[b], 1);
      if (old == BPB - 1) {
        __threadfence();
        float* gs = g_sums + b * 32;
        float* cc = g_cent + b * 24;
        #pragma unroll
        for (int c = 0; c < 8; ++c) {
          float sx = gs[c*4+0], sy = gs[c*4+1], sz = gs[c*4+2], cn = gs[c*4+3];
          float ox, oy, oz;
          if (cn > 0.f) { ox = sx/cn; oy = sy/cn; oz = sz/cn; }
          else          { ox = cc[c*3]; oy = cc[c*3+1]; oz = cc[c*3+2]; }
          cc[c*3] = ox; cc[c*3+1] = oy; cc[c*3+2] = oz;
          gs[c*4] = 0.f; gs[c*4+1] = 0.f; gs[c*4+2] = 0.f; gs[c*4+3] = 0.f;
          if (it == NITER - 1) {
            out[b*24 + c*3 + 0] = ox;
            out[b*24 + c*3 + 1] = oy;
            out[b*24 + c*3 + 2] = oz;
          }
        }
        g_done[b] = 0;
        __threadfence();
        atomicAdd(&g_gen[b], 1);
      }
      int target = it + 1;
      unsigned g;
      do {
        asm volatile("ld.acquire.gpu.u32 %0, [%1];"
                     : "=r"(g) : "l"(&g_gen[b]) : "memory");
        if ((int)g < target) __nanosleep(64);
      } while ((int)g < target);
    }
    __syncthreads();
  }
}

extern "C" void kernel_launch(void* const* d_in, const int* in_sizes, int n_in,
                              void* d_out, int out_size) {
  const float* in = (const float*)d_in[0];
  float* out = (float*)d_out;
  k_init<<<256, 512>>>();
  k_genA<<<4096, 256>>>();
  k_pick<<<BATCHES, 1024>>>();
  k_collect<<<4096, 256>>>();
  k_final<<<BATCHES, 256>>>(in);
  k_lloyd<<<BATCHES * BPB, 256>>>(in, out);
}

// round 16
// speedup vs baseline: 1.1221x; 1.0151x over previous
#include <cuda_runtime.h>
#include <cstdint>

#define BATCHES 64
#define NPTS    (1<<18)
#define NCL     8
#define NITER   10
#define CAND_CAP 1024
#define K2_THRESH (1u<<22)
#define NBUCK 2048
#define LCAP 224
#define BPB 9                 // blocks per batch in persistent Lloyd (576 <= 592 resident)

__device__ unsigned g_key1[(size_t)BATCHES * NPTS];
__device__ unsigned long long g_cand[BATCHES * CAND_CAP];
__device__ int g_cand_cnt[BATCHES];
__device__ uint2 g_sub1[BATCHES], g_sub2[BATCHES];
__device__ int g_hist[BATCHES * NBUCK];
__device__ int g_tbuck[BATCHES * NCL];
__device__ int g_trank[BATCHES * NCL];
__device__ unsigned long long g_list[BATCHES * NCL * LCAP];
__device__ int g_lcnt[BATCHES * NCL];
__device__ float g_cent[BATCHES * NCL * 3];
__device__ float g_sums[BATCHES * NCL * 4];
__device__ int g_done[BATCHES];
__device__ int g_gen[BATCHES];

// ---------------- Threefry-2x32 (JAX-compatible) ----------------
__device__ __forceinline__ void tf2x32(unsigned k0, unsigned k1,
                                       unsigned x0, unsigned x1,
                                       unsigned &o0, unsigned &o1) {
  unsigned k2 = k0 ^ k1 ^ 0x1BD11BDAu;
  x0 += k0; x1 += k1;
#define TF_R(r) { x0 += x1; x1 = __funnelshift_l(x1, x1, (r)); x1 ^= x0; }
  TF_R(13) TF_R(15) TF_R(26) TF_R(6)  x0 += k1; x1 += k2 + 1u;
  TF_R(17) TF_R(29) TF_R(16) TF_R(24) x0 += k2; x1 += k0 + 2u;
  TF_R(13) TF_R(15) TF_R(26) TF_R(6)  x0 += k0; x1 += k1 + 3u;
  TF_R(17) TF_R(29) TF_R(16) TF_R(24) x0 += k1; x1 += k2 + 4u;
  TF_R(13) TF_R(15) TF_R(26) TF_R(6)  x0 += k2; x1 += k0 + 5u;
#undef TF_R
  o0 = x0; o1 = x1;
}

__global__ void k_init() {
  int gid = blockIdx.x * blockDim.x + threadIdx.x;
  if (gid < 64) {
    int b = gid;
    unsigned a0, a1, n0, n1, s0, s1;
    tf2x32(0u, 42u, 0u, (unsigned)b, a0, a1);
    tf2x32(a0, a1, 0u, 0u, n0, n1);
    tf2x32(a0, a1, 0u, 1u, s0, s1);
    g_sub1[b] = make_uint2(s0, s1);
    tf2x32(n0, n1, 0u, 1u, s0, s1);
    g_sub2[b] = make_uint2(s0, s1);
    g_cand_cnt[b] = 0;
    g_done[b] = 0;
    g_gen[b] = 0;
  }
  if (gid < BATCHES * NCL) g_lcnt[gid] = 0;
  if (gid < BATCHES * NBUCK) g_hist[gid] = 0;
}

// key2 candidate filter + key1 store + key1 histogram. 4096 blocks. (proven)
__global__ void __launch_bounds__(256) k_genA() {
  int blk = blockIdx.x;
  int b = blk >> 6;
  unsigned base = (unsigned)(blk & 63) * 4096u;
  uint2 s1 = g_sub1[b], s2 = g_sub2[b];
  int* hist = g_hist + b * NBUCK;
  unsigned* keyp = g_key1 + (size_t)b * NPTS;
  #pragma unroll 4
  for (int k = 0; k < 16; ++k) {
    unsigned i = base + threadIdx.x + (unsigned)k * 256u;
    unsigned y0, y1;
    tf2x32(s2.x, s2.y, 0u, i, y0, y1);
    unsigned k2v = y0 ^ y1;
    if (k2v < K2_THRESH) {
      int slot = atomicAdd(&g_cand_cnt[b], 1);
      if (slot < CAND_CAP)
        g_cand[b * CAND_CAP + slot] = ((unsigned long long)k2v << 32) | i;
    }
    tf2x32(s1.x, s1.y, 0u, i, y0, y1);
    unsigned key = y0 ^ y1;
    keyp[i] = key;
    atomicAdd(&hist[key >> 21], 1);
  }
}

// per batch: top-8 (key2,pos) -> global ranks -> (bucket, in-bucket rank)
__global__ void __launch_bounds__(1024) k_pick() {
  int b = blockIdx.x;
  int t = threadIdx.x;
  __shared__ unsigned long long s_cand[CAND_CAP];
  __shared__ int s_rank[8];
  __shared__ int h[NBUCK];
  __shared__ int c[64];
  __shared__ unsigned long long s_min;

  int cnt = g_cand_cnt[b]; if (cnt > CAND_CAP) cnt = CAND_CAP;
  s_cand[t] = (t < cnt) ? g_cand[b * CAND_CAP + t] : ~0ull;
  h[t] = g_hist[b * NBUCK + t];
  h[t + 1024] = g_hist[b * NBUCK + t + 1024];
  __syncthreads();
  for (int k = 0; k < 8; ++k) {
    if (t == 0) s_min = ~0ull;
    __syncthreads();
    atomicMin(&s_min, s_cand[t]);
    __syncthreads();
    unsigned long long m = s_min;
    if (t == 0) s_rank[k] = (int)(m & 0xffffffffull);
    if (s_cand[t] == m) s_cand[t] = ~0ull;
    __syncthreads();
  }
  if (t < 64) {
    int s = 0;
    #pragma unroll
    for (int q = 0; q < 32; ++q) s += h[t * 32 + q];
    c[t] = s;
  }
  __syncthreads();
  if (t == 0) {
    int run = 0;
    for (int w = 0; w < 64; ++w) { int v = c[w]; c[w] = run; run += v; }
  }
  __syncthreads();
  if (t < 8) {
    int r = s_rank[t];
    int w = 0;
    for (int q = 0; q < 64; ++q) if (c[q] <= r) w = q;
    int rem = r - c[w];
    int d = w * 32;
    for (int q = 0; q < 32; ++q) {
      int hv = h[w * 32 + q];
      if (rem < hv) { d = w * 32 + q; break; }
      rem -= hv;
    }
    g_tbuck[b * 8 + t] = d;
    g_trank[b * 8 + t] = rem;
  }
}

// scan stored key1, bucket bitmap fast-path (MLP 8), collect target buckets.
__global__ void __launch_bounds__(256) k_collect() {
  int blk = blockIdx.x;
  int b = blk >> 6;
  unsigned base = (unsigned)(blk & 63) * 4096u;
  const unsigned* __restrict__ keyp = g_key1 + (size_t)b * NPTS;
  __shared__ unsigned bm[NBUCK / 32];     // 2048-bit bucket membership bitmap
  int tb[8];
  #pragma unroll
  for (int j = 0; j < 8; ++j) tb[j] = g_tbuck[b * 8 + j];
  if (threadIdx.x < 64) bm[threadIdx.x] = 0u;
  __syncthreads();
  if (threadIdx.x < 8) {
    int d = tb[threadIdx.x];
    atomicOr(&bm[d >> 5], 1u << (d & 31));
  }
  __syncthreads();
  #pragma unroll 8
  for (int k = 0; k < 16; ++k) {
    unsigned i = base + threadIdx.x + (unsigned)k * 256u;
    unsigned key = keyp[i];
    unsigned bu = key >> 21;
    if ((bm[bu >> 5] >> (bu & 31)) & 1u) {       // rare (~8/2048 buckets)
      #pragma unroll
      for (int j = 0; j < 8; ++j)
        if ((int)bu == tb[j]) {
          int s = atomicAdd(&g_lcnt[b * 8 + j], 1);
          if (s < LCAP)
            g_list[(b * 8 + j) * LCAP + s] =
                ((unsigned long long)(key & 0x1FFFFFu) << 32) | i;
        }
    }
  }
}

// per (batch,target): pick rank-r entry by (key1_low, idx); write centroid.
__global__ void __launch_bounds__(256) k_final(const float* __restrict__ in) {
  int b = blockIdx.x;
  int t = threadIdx.x;
  int j = t >> 5, lane = t & 31;
  __shared__ unsigned long long sl[8][LCAP];
  int n = g_lcnt[b * 8 + j]; if (n > LCAP) n = LCAP;
  for (int q = lane; q < n; q += 32)
    sl[j][q] = g_list[(b * 8 + j) * LCAP + q];
  __syncwarp();
  int r = g_trank[b * 8 + j];
  for (int q = lane; q < n; q += 32) {
    unsigned long long e = sl[j][q];
    int rk = 0;
    for (int p = 0; p < n; ++p) rk += (sl[j][p] < e);
    if (rk == r) {
      unsigned idx = (unsigned)(e & 0xffffffffull);
      const float* px = in + ((size_t)b * NPTS + idx) * 3;
      float* cc = g_cent + (b * 8 + j) * 3;
      cc[0] = px[0]; cc[1] = px[1]; cc[2] = px[2];
    }
  }
  if (t < 32) g_sums[b * 32 + t] = 0.f;
}

// ---- persistent Lloyd: direct float4 LDG, barrier-free inner loop ----
// (byte-identical to the 697us R13 kernel — do not touch)
__global__ void __launch_bounds__(256, 4) k_lloyd(const float* __restrict__ in,
                                                  float* __restrict__ out) {
  int b   = blockIdx.x / BPB;
  int blk = blockIdx.x - b * BPB;
  int tid = threadIdx.x;
  __shared__ float s_acc[8][4][256];    // 32 KB only

  int ch0 = blk * 28 + min(blk, 4);
  int nch = 28 + (blk < 4 ? 1 : 0);     // 1024-pt groups owned by this block
  const float4* gp = (const float4*)in + (size_t)b * (NPTS*3/4)
                                       + (size_t)ch0 * 768;

  for (int it = 0; it < NITER; ++it) {
    float n0[8], n1[8], n2[8], bb[8];
    const float* cent = g_cent + b * 24;
    #pragma unroll
    for (int c = 0; c < 8; ++c) {
      float a = cent[c*3+0], d = cent[c*3+1], e = cent[c*3+2];
      n0[c] = -2.f*a; n1[c] = -2.f*d; n2[c] = -2.f*e;
      bb[c] = a*a + d*d + e*e + 6.f;   // positive scores: uint cmp == float cmp
    }
    for (int i = tid; i < 8*4*256; i += 256) (&s_acc[0][0][0])[i] = 0.f;
    __syncthreads();   // accumulators zeroed before any thread writes

    unsigned long long cnt8 = 0ull;    // 8x 8-bit per-cluster counters (max 116)

    // barrier-free: each thread owns its accumulator column; 4 pts per group
    const float4* tp = gp + tid * 3;
    #pragma unroll 2
    for (int g = 0; g < nch; ++g) {
      float4 A = tp[0], B4 = tp[1], C = tp[2];
      tp += 768;
      float qx[4] = {A.x, A.w, B4.z, C.y};
      float qy[4] = {A.y, B4.x, B4.w, C.z};
      float qz[4] = {A.z, B4.y, C.x,  C.w};
      #pragma unroll
      for (int q = 0; q < 4; ++q) {
        float x0 = qx[q], x1 = qy[q], x2 = qz[q];
        unsigned u[8];
        #pragma unroll
        for (int c = 0; c < 8; ++c) {
          float s = fmaf(x2, n2[c], fmaf(x1, n1[c], fmaf(x0, n0[c], bb[c])));
          u[c] = (__float_as_uint(s) & 0xFFFFFFF8u) | (unsigned)c;
        }
        unsigned m = min(min(min(u[0],u[1]),min(u[2],u[3])),
                         min(min(u[4],u[5]),min(u[6],u[7])));
        unsigned bi = m & 7u;
        float* a = &s_acc[0][0][0] + bi * 1024 + tid;
        a[0]   += x0;
        a[256] += x1;
        a[512] += x2;
        cnt8 += 1ull << (bi << 3);
      }
    }
    // expand packed counts into the count plane (once per iteration)
    #pragma unroll
    for (int c = 0; c < 8; ++c)
      s_acc[c][3][tid] = (float)((unsigned)(cnt8 >> (c << 3)) & 255u);
    __syncthreads();

    int w = tid >> 5, lane = tid & 31;   // warp w reduces cluster w
    float r0=0.f, r1=0.f, r2=0.f, r3=0.f;
    #pragma unroll
    for (int k = 0; k < 8; ++k) {
      r0 += s_acc[w][0][lane + 32*k];
      r1 += s_acc[w][1][lane + 32*k];
      r2 += s_acc[w][2][lane + 32*k];
      r3 += s_acc[w][3][lane + 32*k];
    }
    #pragma unroll
    for (int o = 16; o; o >>= 1) {
      r0 += __shfl_down_sync(0xffffffffu, r0, o);
      r1 += __shfl_down_sync(0xffffffffu, r1, o);
      r2 += __shfl_down_sync(0xffffffffu, r2, o);
      r3 += __shfl_down_sync(0xffffffffu, r3, o);
    }
    if (lane == 0) {
      float* gs = g_sums + b * 32 + w * 4;
      atomicAdd(gs+0, r0); atomicAdd(gs+1, r1);
      atomicAdd(gs+2, r2); atomicAdd(gs+3, r3);
      __threadfence();
    }
    __syncthreads();

    if (tid == 0) {
      int old = atomicAdd(&g_done[b], 1);
      if (old == BPB - 1) {
        __threadfence();
        float* gs = g_sums + b * 32;
        float* cc = g_cent + b * 24;
        #pragma unroll
        for (int c = 0; c < 8; ++c) {
          float sx = gs[c*4+0], sy = gs[c*4+1], sz = gs[c*4+2], cn = gs[c*4+3];
          float ox, oy, oz;
          if (cn > 0.f) { ox = sx/cn; oy = sy/cn; oz = sz/cn; }
          else          { ox = cc[c*3]; oy = cc[c*3+1]; oz = cc[c*3+2]; }
          cc[c*3] = ox; cc[c*3+1] = oy; cc[c*3+2] = oz;
          gs[c*4] = 0.f; gs[c*4+1] = 0.f; gs[c*4+2] = 0.f; gs[c*4+3] = 0.f;
          if (it == NITER - 1) {
            out[b*24 + c*3 + 0] = ox;
            out[b*24 + c*3 + 1] = oy;
            out[b*24 + c*3 + 2] = oz;
          }
        }
        g_done[b] = 0;
        __threadfence();
        atomicAdd(&g_gen[b], 1);
      }
      int target = it + 1;
      unsigned g;
      do {
        asm volatile("ld.acquire.gpu.u32 %0, [%1];"
                     : "=r"(g) : "l"(&g_gen[b]) : "memory");
        if ((int)g < target) __nanosleep(64);
      } while ((int)g < target);
    }
    __syncthreads();
  }
}

extern "C" void kernel_launch(void* const* d_in, const int* in_sizes, int n_in,
                              void* d_out, int out_size) {
  const float* in = (const float*)d_in[0];
  float* out = (float*)d_out;
  k_init<<<256, 512>>>();
  k_genA<<<4096, 256>>>();
  k_pick<<<BATCHES, 1024>>>();
  k_collect<<<4096, 256>>>();
  k_final<<<BATCHES, 256>>>(in);
  k_lloyd<<<BATCHES * BPB, 256>>>(in, out);
}